// round 9
// baseline (speedup 1.0000x reference)
#include <cuda_runtime.h>
#include <math.h>

#define TT 256
#define DD 512
#define HH 256
#define EE 256
#define VV 8192
#define G3 768           // 3*H
#define DH (DD*HH)
#define NG 16            // static row groups of 32 rows
#define OFFG (256*96)    // sB group stride in floats (grp0 -> grp1)

// Scratch (static device globals; no runtime allocation).
__device__ float g_P[2][(size_t)VV * G3];   // emb@Wih^T + biases, [sel][v][3H]
__device__ int   g_perm[TT * DD];           // per-step, per-group bucketed row ids
__device__ int   g_cnt1[TT * NG];           // grp1 count per (t, group)
__device__ int   g_e_is_i32;
__device__ unsigned int g_arr_rg[NG * 32];  // per-group arrive counters (128B apart)
__device__ unsigned int g_ep_rg[NG * 32];   // per-group epochs

// ---------------------------------------------------------------------------
// Packed f32x2 helpers
// ---------------------------------------------------------------------------
__device__ __forceinline__ unsigned long long dup2(float b) {
    unsigned long long r;
    asm("mov.b64 %0, {%1, %1};" : "=l"(r) : "r"(__float_as_uint(b)));
    return r;
}
__device__ __forceinline__ void fma2(unsigned long long& acc, unsigned long long a, unsigned long long b) {
    asm("fma.rn.f32x2 %0, %1, %2, %0;" : "+l"(acc) : "l"(a), "l"(b));
}
__device__ __forceinline__ void add2(unsigned long long& acc, unsigned long long o) {
    asm("add.rn.f32x2 %0, %0, %1;" : "+l"(acc) : "l"(o));
}
__device__ __forceinline__ float lo32(unsigned long long v) {
    unsigned int l, h; asm("mov.b64 {%0, %1}, %2;" : "=r"(l), "=r"(h) : "l"(v));
    return __uint_as_float(l);
}
__device__ __forceinline__ float hi32(unsigned long long v) {
    unsigned int l, h; asm("mov.b64 {%0, %1}, %2;" : "=r"(l), "=r"(h) : "l"(v));
    return __uint_as_float(h);
}

// ---------------------------------------------------------------------------
__global__ void detect_edges_kernel(const unsigned char* __restrict__ e) {
    int i32 = 1;
    for (int k = 0; k < 256; ++k)
        if (e[4 * k + 1] | e[4 * k + 2] | e[4 * k + 3]) { i32 = 0; break; }
    g_e_is_i32 = i32;
}

// Per-timestep, per-32-row-group bucketing: grp1 rows first, grp0 from the end.
__global__ void bucket_kernel(const void* __restrict__ edges) {
    int t = threadIdx.x;
    if (t >= TT) return;
    const int is_i32 = g_e_is_i32;
    const unsigned char* e8  = (const unsigned char*)edges + (size_t)t * DD;
    const int*           e32 = (const int*)edges + (size_t)t * DD;
    for (int rg = 0; rg < NG; ++rg) {
        int base = rg * 32;
        int* p = g_perm + (size_t)t * DD + base;
        int i1 = 0, i0 = 0;
        for (int i = 0; i < 32; ++i) {
            int d = base + i;
            bool ev = is_i32 ? (e32[d] != 0) : (e8[d] != 0);
            if (ev) p[i1++] = d;
            else    p[31 - (i0++)] = d;
        }
        g_cnt1[t * NG + rg] = i1;
    }
}

// ---------------------------------------------------------------------------
// P[sel][v][j] = dot(emb[v], Wih[j]) + bih[j] + (j < 2H ? bhh[j] : 0)
// ---------------------------------------------------------------------------
__global__ void precompute_P_kernel(
    const float* __restrict__ emb,
    const float* __restrict__ cWih, const float* __restrict__ cbih, const float* __restrict__ cbhh,
    const float* __restrict__ sWih, const float* __restrict__ sbih, const float* __restrict__ sbhh)
{
    int sel = blockIdx.z;
    const float* Wih = sel ? cWih : sWih;
    const float* bih = sel ? cbih : sbih;
    const float* bhh = sel ? cbhh : sbhh;
    float* P = g_P[sel];

    __shared__ __align__(16) float As[32][64];
    __shared__ __align__(16) float Bs[32][64];

    int vbase = blockIdx.y * 64;
    int jbase = blockIdx.x * 64;
    int tid  = threadIdx.x;
    int rowg = tid >> 4;
    int colg = tid & 15;

    unsigned long long acc[2][4];
#pragma unroll
    for (int i = 0; i < 2; ++i)
#pragma unroll
        for (int j = 0; j < 4; ++j) acc[i][j] = 0ull;

    for (int kb = 0; kb < EE; kb += 32) {
#pragma unroll
        for (int i = 0; i < 2; ++i) {
            int lin = tid + i * 256;
            int m  = lin >> 3;
            int k4 = (lin & 7) << 2;
            float4 v = *(const float4*)&emb[(size_t)(vbase + m) * EE + kb + k4];
            As[k4 + 0][m] = v.x; As[k4 + 1][m] = v.y; As[k4 + 2][m] = v.z; As[k4 + 3][m] = v.w;
            float4 w = *(const float4*)&Wih[(size_t)(jbase + m) * EE + kb + k4];
            Bs[k4 + 0][m] = w.x; Bs[k4 + 1][m] = w.y; Bs[k4 + 2][m] = w.z; Bs[k4 + 3][m] = w.w;
        }
        __syncthreads();
#pragma unroll 8
        for (int k = 0; k < 32; ++k) {
            ulonglong2 av = *(const ulonglong2*)&As[k][rowg * 4];
            float4 b = *(const float4*)&Bs[k][colg * 4];
            unsigned long long b0 = dup2(b.x), b1 = dup2(b.y), b2 = dup2(b.z), b3 = dup2(b.w);
            fma2(acc[0][0], av.x, b0); fma2(acc[1][0], av.y, b0);
            fma2(acc[0][1], av.x, b1); fma2(acc[1][1], av.y, b1);
            fma2(acc[0][2], av.x, b2); fma2(acc[1][2], av.y, b2);
            fma2(acc[0][3], av.x, b3); fma2(acc[1][3], av.y, b3);
        }
        __syncthreads();
    }

#pragma unroll
    for (int i = 0; i < 2; ++i) {
        int v0 = vbase + rowg * 4 + i * 2;
#pragma unroll
        for (int j = 0; j < 4; ++j) {
            int jj = jbase + colg * 4 + j;
            float bias = bih[jj] + (jj < 2 * HH ? bhh[jj] : 0.f);
            P[(size_t)v0 * G3 + jj]       = lo32(acc[i][j]) + bias;
            P[(size_t)(v0 + 1) * G3 + jj] = hi32(acc[i][j]) + bias;
        }
    }
}

extern __shared__ float dyn_smem[];

// ---------------------------------------------------------------------------
// K=64 quarter loop. Pairs p < N1P use grp1 weights, rest grp0 (compile-time).
// ---------------------------------------------------------------------------
template<int N1P>
__device__ __forceinline__ void kloop64(
    const float* __restrict__ Apt, int r8,
    const float* __restrict__ B1, const float* __restrict__ B0,
    unsigned long long acc[3][4])
{
#pragma unroll 8
    for (int kk = 0; kk < 64; ++kk) {
        int sw = kk & 28;
        ulonglong2 a01 = *(const ulonglong2*)(Apt + kk * 32 + (r8 ^ sw));
        ulonglong2 a23 = *(const ulonglong2*)(Apt + kk * 32 + ((r8 + 4) ^ sw));
        unsigned long long b1_0 = 0, b1_1 = 0, b1_2 = 0;
        unsigned long long b0_0 = 0, b0_1 = 0, b0_2 = 0;
        if (N1P > 0) { const float* b = B1 + kk * 96; b1_0 = dup2(b[0]); b1_1 = dup2(b[1]); b1_2 = dup2(b[2]); }
        if (N1P < 4) { const float* b = B0 + kk * 96; b0_0 = dup2(b[0]); b0_1 = dup2(b[1]); b0_2 = dup2(b[2]); }
#define PAIRF(p, av) \
        if ((p) < N1P) { fma2(acc[0][p], av, b1_0); fma2(acc[1][p], av, b1_1); fma2(acc[2][p], av, b1_2); } \
        else           { fma2(acc[0][p], av, b0_0); fma2(acc[1][p], av, b0_1); fma2(acc[2][p], av, b0_2); }
        PAIRF(0, a01.x)
        PAIRF(1, a01.y)
        PAIRF(2, a23.x)
        PAIRF(3, a23.y)
#undef PAIRF
    }
}

// ---------------------------------------------------------------------------
// Persistent recurrent kernel. Grid (8 u-tiles, 16 row-groups) = 128 blocks.
// Rows are STATIC per group (d in [32rg, 32rg+32)) -> sync scope is only the
// 8 u-tile blocks of the same group (cheap 8-way barrier, no global skew).
// Per step rows are bucketed within the group; warps are grp-homogeneous
// except at most one straddling warp per quarter (templated k-loop + K=64
// fix-up mini-loop for the single odd-boundary row).
// ---------------------------------------------------------------------------
__global__ void __launch_bounds__(512, 1) persistent_kernel(
    const float* __restrict__ h0,              // [D,H]
    float* __restrict__ out,                   // [T,D,H]
    const int* __restrict__ nodes,             // [T,D]
    const float* __restrict__ cWhh, const float* __restrict__ cbhh,
    const float* __restrict__ sWhh, const float* __restrict__ sbhh)
{
    float* sB = dyn_smem;                       // [2][256][96]
    float* sA = dyn_smem + 2 * 256 * 96;        // [256][32] swizzled; bufs + C overlay
    unsigned long long* sPq = (unsigned long long*)sA;
    float* sC = sA;                             // C [32][96] overlays bufA

    __shared__ int Rs[32];
    __shared__ int Ns[32];
    __shared__ float s_bnb[2][32];
    __shared__ unsigned int s_e0;

    int tid  = threadIdx.x;
    int u0   = blockIdx.x * 32;
    int rg   = blockIdx.y;
    int w    = tid >> 5;
    int lane = tid & 31;
    int q    = w & 3;              // K-quarter (spreads straddle warps across SMSPs)
    int rowg = w >> 2;             // row-octet 0..3
    int colg = lane;               // cols colg*3..+2
    int otid = rowg * 32 + colg;   // output sub-tile id 0..127
    int r8   = rowg * 8;
    int qoff = q << 6;

    if (tid == 0) s_e0 = *(volatile unsigned int*)&g_ep_rg[rg * 32];

    // ---- prologue: load both Whh slices into smem (once) ----
    for (int g = 0; g < 2; ++g) {
        const float* W = g ? cWhh : sWhh;
        for (int idx = tid; idx < 96 * 64; idx += 512) {   // 96 cols x 64 float4
            int c  = idx >> 6;
            int k4 = (idx & 63) << 2;
            int wr = ((c >> 5) << 8) + u0 + (c & 31);
            float4 v = *(const float4*)&W[(size_t)wr * HH + k4];
            float* b = sB + ((size_t)g * 256 + k4) * 96 + c;
            b[0 * 96] = v.x; b[1 * 96] = v.y; b[2 * 96] = v.z; b[3 * 96] = v.w;
        }
    }
    if (tid < 64) {
        int g = tid >> 5, ui = tid & 31;
        s_bnb[g][ui] = (g ? cbhh : sbhh)[2 * HH + u0 + ui];
    }
    __syncthreads();

    unsigned int e0 = s_e0;

    // epilogue element assignment: elems e = tid, tid+512 -> (slot, unit)
    int em0 = tid >> 5,          eu0 = tid & 31;
    int em1 = (tid + 512) >> 5,  eu1 = (tid + 512) & 31;

    for (int t = 0; t < TT; ++t) {
        const float* h_prev = (t == 0) ? h0 : (out + (size_t)(t - 1) * DH);
        float*       h_out  = out + (size_t)t * DH;

        int j = g_cnt1[t * NG + rg];           // grp1 prefix length in this group

        if (tid < 32) {
            int d = g_perm[(size_t)t * DD + rg * 32 + tid];
            Rs[tid] = d;
            Ns[tid] = nodes[(size_t)t * DD + d];
        }
        __syncthreads();

        // ---- prefetch epilogue operands (overlap with gather + k-loop) ----
        int eg0 = (em0 < j) ? 1 : 0;
        int eg1 = (em1 < j) ? 1 : 0;
        const float* Pp0 = g_P[eg0] + (size_t)Ns[em0] * G3 + u0;
        const float* Pp1 = g_P[eg1] + (size_t)Ns[em1] * G3 + u0;
        float pf_gr0 = __ldg(Pp0 + eu0);
        float pf_gz0 = __ldg(Pp0 + HH + eu0);
        float pf_gn0 = __ldg(Pp0 + 2 * HH + eu0);
        float pf_hp0 = __ldg(h_prev + (size_t)Rs[em0] * HH + u0 + eu0);
        float pf_gr1 = __ldg(Pp1 + eu1);
        float pf_gz1 = __ldg(Pp1 + HH + eu1);
        float pf_gn1 = __ldg(Pp1 + 2 * HH + eu1);
        float pf_hp1 = __ldg(h_prev + (size_t)Rs[em1] * HH + u0 + eu1);

        // ---- gather A: 32 rows x 256 K into swizzled sA ----
#pragma unroll
        for (int i = 0; i < 4; ++i) {
            int lin = tid + i * 512;
            int m = lin >> 6;
            int k = (lin & 63) << 2;
            float4 v = *(const float4*)&h_prev[(size_t)Rs[m] * HH + k];
            int ms = m ^ (k & 28);
            sA[(k + 0) * 32 + ms] = v.x;
            sA[(k + 1) * 32 + ms] = v.y;
            sA[(k + 2) * 32 + ms] = v.z;
            sA[(k + 3) * 32 + ms] = v.w;
        }
        __syncthreads();

        // ---- warp grp structure ----
        int v = j - r8;                                   // grp1 rows in this warp
        int n1p   = (v >= 8) ? 4 : ((v <= 0) ? 0 : ((v + 1) >> 1));
        bool strad = (v > 0) && (v < 8) && (v & 1);
        int p_m   = (v - 1) >> 1;                         // straddle pair (if strad)

        const float* Apt = sA + qoff * 32;
        const float* B0p = sB + qoff * 96 + colg * 3;     // grp0 (sibling)
        const float* B1p = B0p + OFFG;                    // grp1 (child)

        unsigned long long acc[3][4];
#pragma unroll
        for (int jj = 0; jj < 3; ++jj)
#pragma unroll
            for (int p = 0; p < 4; ++p) acc[jj][p] = 0ull;

        switch (n1p) {
            case 0: kloop64<0>(Apt, r8, B1p, B0p, acc); break;
            case 1: kloop64<1>(Apt, r8, B1p, B0p, acc); break;
            case 2: kloop64<2>(Apt, r8, B1p, B0p, acc); break;
            case 3: kloop64<3>(Apt, r8, B1p, B0p, acc); break;
            default: kloop64<4>(Apt, r8, B1p, B0p, acc); break;
        }

        // ---- straddle fix-up: recompute the odd row's pair with grp0 B ----
        unsigned long long ax[3] = {0ull, 0ull, 0ull};
        if (strad) {
            int mrow = r8 + 2 * p_m;
#pragma unroll 8
            for (int kk = 0; kk < 64; ++kk) {
                int sw = kk & 28;
                unsigned long long a = *(const unsigned long long*)(Apt + kk * 32 + (mrow ^ sw));
                const float* b = B0p + kk * 96;
                fma2(ax[0], a, dup2(b[0]));
                fma2(ax[1], a, dup2(b[1]));
                fma2(ax[2], a, dup2(b[2]));
            }
        }
        __syncthreads();     // all sA reads done before buffer overlay

        // ---- combine quarters; bufs [128][15] u64 (stride 15 avoids conflicts)
        unsigned long long* bufA = sPq;          // 15360 B
        unsigned long long* bufB = sPq + 1920;   // 15360 B
        if (q == 1) {
            unsigned long long* wp = bufA + otid * 15;
#pragma unroll
            for (int jj = 0; jj < 3; ++jj)
#pragma unroll
                for (int p = 0; p < 4; ++p) wp[jj * 4 + p] = acc[jj][p];
            if (strad) { wp[12] = ax[0]; wp[13] = ax[1]; wp[14] = ax[2]; }
        } else if (q == 3) {
            unsigned long long* wp = bufB + otid * 15;
#pragma unroll
            for (int jj = 0; jj < 3; ++jj)
#pragma unroll
                for (int p = 0; p < 4; ++p) wp[jj * 4 + p] = acc[jj][p];
            if (strad) { wp[12] = ax[0]; wp[13] = ax[1]; wp[14] = ax[2]; }
        }
        __syncthreads();
        if (q == 0) {
            const unsigned long long* r = bufA + otid * 15;
#pragma unroll
            for (int jj = 0; jj < 3; ++jj)
#pragma unroll
                for (int p = 0; p < 4; ++p) add2(acc[jj][p], r[jj * 4 + p]);
            if (strad) { add2(ax[0], r[12]); add2(ax[1], r[13]); add2(ax[2], r[14]); }
        } else if (q == 2) {
            unsigned long long* rw = bufB + otid * 15;
#pragma unroll
            for (int jj = 0; jj < 3; ++jj)
#pragma unroll
                for (int p = 0; p < 4; ++p) { add2(acc[jj][p], rw[jj * 4 + p]); rw[jj * 4 + p] = acc[jj][p]; }
            if (strad) {
                add2(ax[0], rw[12]); add2(ax[1], rw[13]); add2(ax[2], rw[14]);
                rw[12] = ax[0]; rw[13] = ax[1]; rw[14] = ax[2];
            }
        }
        __syncthreads();
        if (q == 0) {
            const unsigned long long* r = bufB + otid * 15;
#pragma unroll
            for (int jj = 0; jj < 3; ++jj)
#pragma unroll
                for (int p = 0; p < 4; ++p) add2(acc[jj][p], r[jj * 4 + p]);
            if (strad) { add2(ax[0], r[12]); add2(ax[1], r[13]); add2(ax[2], r[14]); }
            // stage C [32][96] (overlays bufA; bufA reads finished last window)
#pragma unroll
            for (int jj = 0; jj < 3; ++jj)
#pragma unroll
                for (int p = 0; p < 4; ++p) {
                    int r0 = r8 + p * 2;
                    sC[(size_t)r0 * 96 + colg * 3 + jj] = lo32(acc[jj][p]);
                    float hv = hi32(acc[jj][p]);
                    if (strad && p == p_m) hv = hi32(ax[jj]);   // odd-boundary row
                    sC[(size_t)(r0 + 1) * 96 + colg * 3 + jj] = hv;
                }
        }
        __syncthreads();

        // ---- GRU gate epilogue: 1024 elems, 2 per thread ----
        {
            float hr = sC[em0 * 96 + eu0];
            float hz = sC[em0 * 96 + 32 + eu0];
            float hn = sC[em0 * 96 + 64 + eu0] + s_bnb[eg0][eu0];
            float r = 1.f / (1.f + __expf(-(pf_gr0 + hr)));
            float z = 1.f / (1.f + __expf(-(pf_gz0 + hz)));
            float n = tanhf(pf_gn0 + r * hn);
            h_out[(size_t)Rs[em0] * HH + u0 + eu0] = (1.f - z) * n + z * pf_hp0;
        }
        {
            float hr = sC[em1 * 96 + eu1];
            float hz = sC[em1 * 96 + 32 + eu1];
            float hn = sC[em1 * 96 + 64 + eu1] + s_bnb[eg1][eu1];
            float r = 1.f / (1.f + __expf(-(pf_gr1 + hr)));
            float z = 1.f / (1.f + __expf(-(pf_gz1 + hz)));
            float n = tanhf(pf_gn1 + r * hn);
            h_out[(size_t)Rs[em1] * HH + u0 + eu1] = (1.f - z) * n + z * pf_hp1;
        }

        // ---- 8-way group barrier (skip after final step) ----
        __syncthreads();                        // all stores issued before signal
        if (t < TT - 1) {
            if (tid == 0) {
                __threadfence();
                unsigned int old = atomicAdd(&g_arr_rg[rg * 32], 1u);
                if (old == 7) {
                    g_arr_rg[rg * 32] = 0;
                    __threadfence();
                    atomicAdd(&g_ep_rg[rg * 32], 1u);
                }
                while (((*(volatile unsigned int*)&g_ep_rg[rg * 32]) - e0) < (unsigned int)(t + 1)) { }
                __threadfence();
            }
            __syncthreads();
        }
    }
}

// ---------------------------------------------------------------------------
extern "C" void kernel_launch(void* const* d_in, const int* in_sizes, int n_in,
                              void* d_out, int out_size) {
    const int*           nodes = (const int*)d_in[0];
    const void*          edges = d_in[1];
    const float*         h0    = (const float*)d_in[2];
    const float*         emb   = (const float*)d_in[3];
    const float*         cWih  = (const float*)d_in[4];
    const float*         cWhh  = (const float*)d_in[5];
    const float*         cbih  = (const float*)d_in[6];
    const float*         cbhh  = (const float*)d_in[7];
    const float*         sWih  = (const float*)d_in[8];
    const float*         sWhh  = (const float*)d_in[9];
    const float*         sbih  = (const float*)d_in[10];
    const float*         sbhh  = (const float*)d_in[11];
    float* out = (float*)d_out;

    detect_edges_kernel<<<1, 1>>>((const unsigned char*)edges);
    bucket_kernel<<<1, 256>>>(edges);

    dim3 gP(G3 / 64, VV / 64, 2);
    precompute_P_kernel<<<gP, 256>>>(emb, cWih, cbih, cbhh, sWih, sbih, sbhh);

    static int smem_bytes = (2 * 256 * 96 + 256 * 32) * 4;   // 229376
    cudaFuncSetAttribute(persistent_kernel,
                         cudaFuncAttributeMaxDynamicSharedMemorySize, smem_bytes);
    persistent_kernel<<<dim3(8, NG), 512, smem_bytes>>>(
        h0, out, nodes, cWhh, cbhh, sWhh, sbhh);

    cudaMemcpyAsync(out + (size_t)TT * DH, out + (size_t)(TT - 1) * DH,
                    (size_t)DH * sizeof(float), cudaMemcpyDeviceToDevice, 0);
}